// round 13
// baseline (speedup 1.0000x reference)
#include <cuda_runtime.h>
#include <math.h>

// Problem constants (N=128 images, P=16 control points, S=128 grid)
#define NIMG 128
#define NP   16
#define NSEG (NP-1)            // 15 segments
#define SDIM 128
#define RAD  4                 // 9-tap Gaussian: dropped taps <= 1.1e-7 (safe vs 1e-3 tol)
#define KW   (2*RAD+1)

#define BT     256             // threads per CTA
#define SLICES 8               // CTAs per image
#define SR     16              // output rows per CTA
#define LR     (SR + 2*RAD)    // 24 histogram rows per slice (with halo)
#define HP     132             // hist y pitch (y in 0..128), mult of 4
#define M1P    140             // m1 pitch, mult of 4 (cols 0..136 used; 137..139 pad)
#define PTS_F  (NP*2)          // 32 floats of control points
#define HS_F   (LR*HP)         // 3168
#define M1_F   (SR*M1P)        // 2240
#define SMEM_F (HS_F + M1_F + PTS_F)   // 5440 floats = 21.76 KB -> 8 CTAs/SM

// tanh(x) for x>=0; for x<=0.01, tanh(x)=x within 3.3e-7 abs
__device__ __forceinline__ float tanh_pos(float x) {
    if (x > 0.01f) {
        float e = __expf(x + x);                  // inf-safe: e=inf -> result 1
        x = 1.0f - __fdividef(2.0f, e + 1.0f);
    }
    return x;
}

__global__ __launch_bounds__(BT, 8)
void plotline2_kernel(const float* __restrict__ points, float* __restrict__ out)
{
    extern __shared__ float sm[];
    float* hs  = sm;                 // [LR][HP]
    float* m1  = sm + HS_F;          // [SR][M1P]; col c holds conv-x at y = c-4
    float* pts = sm + HS_F + M1_F;   // [NP*2]

    const int n   = blockIdx.x >> 3;
    const int q   = blockIdx.x & 7;
    const int s0  = q * SR;
    const int tid = threadIdx.x;

    // Compile-time taps exp(-d^2) -> FFMA immediates
    constexpr float W[KW] = {
        1.1253517471925912e-7f, 1.2340980408667956e-4f, 0.018315638888734179f,
        0.36787944117144233f, 1.0f, 0.36787944117144233f,
        0.018315638888734179f, 1.2340980408667956e-4f, 1.1253517471925912e-7f
    };

    // ---- zero hs+m1 (contiguous, mult of 4) + preload points ----
    {
        float4 z = make_float4(0.f, 0.f, 0.f, 0.f);
        float4* p4 = (float4*)sm;
        for (int i = tid; i < (HS_F + M1_F) / 4; i += BT) p4[i] = z;
        if (tid < PTS_F) pts[tid] = points[n * PTS_F + tid];
    }
    __syncthreads();

    // ---- stage 1: interpolate 1920 points, histogram those in our x-window ----
    // Permuted mapping (seg = idx%15): warp lanes spread over 15 segments ->
    // spread-address smem atomics.
    const float inv = 1.0f / (float)SDIM;
    const int lrbase = s0 - RAD;
    for (int idx = tid; idx < NSEG * SDIM; idx += BT) {
        int i   = idx / NSEG;              // 0..127 (step)
        int seg = idx - i * NSEG;          // 0..14  (segment)
        float t   = (float)i * inv;
        float omt = 1.0f - t;
        float x0 = pts[seg * 2 + 0];
        float x1 = pts[seg * 2 + 2];
        // match XLA: mul, mul, add — no fma contraction
        float x = __fadd_rn(__fmul_rn(omt, x0), __fmul_rn(t, x1));
        int ix = (int)rintf(x);            // round-half-to-even, 0..128
        int lr = ix - lrbase;              // local hist row
        if ((unsigned)lr < (unsigned)LR) { // early-out (most points skip)
            float y0 = pts[seg * 2 + 1];
            float y1 = pts[seg * 2 + 3];
            float y = __fadd_rn(__fmul_rn(omt, y0), __fmul_rn(t, y1));
            int iy = (int)rintf(y);
            atomicAdd(&hs[lr * HP + iy], 1.0f);
        }
    }
    __syncthreads();

    // ---- stage 2: conv over x: m1[s][y+4] = sum_d W[d]*hs[s+d][y] ----
    // 4-row groups; lanes -> consecutive y (stride 1, conflict-free).
    for (int item = tid; item < 4 * 129; item += BT) {
        int g = item / 129;                // row group 0..3
        int y = item - g * 129;            // 0..128
        int sb = g * 4;
        float v[4 + KW - 1];               // 12
#pragma unroll
        for (int j = 0; j < 4 + KW - 1; ++j)
            v[j] = hs[(sb + j) * HP + y];
#pragma unroll
        for (int i = 0; i < 4; ++i) {
            float acc = 0.0f;
#pragma unroll
            for (int d = 0; d < KW; ++d)
                acc = fmaf(W[d], v[i + d], acc);
            m1[(sb + i) * M1P + (y + RAD)] = acc;
        }
    }
    __syncthreads();

    // ---- stage 3: conv over t + tanh -> DIRECT coalesced gmem store ----
    // Warp w handles rows s = w and w+8. Lane l -> t = 4l..4l+3.
    // Needs m1 cols t..t+8 -> three aligned LDS.128 at 4l, 4l+4, 4l+8
    // (contiguous across lanes: conflict-free). One STG.128 per row: the
    // warp's 32x16B = full 512B row, perfectly coalesced.
    {
        const int w = tid >> 5;
        const int l = tid & 31;
        float* outn = out + ((size_t)n * SDIM + s0) * SDIM;
#pragma unroll
        for (int rr = 0; rr < 2; ++rr) {
            int s = w + rr * 8;
            const float* row = m1 + s * M1P + 4 * l;
            float4 a = *(const float4*)(row);
            float4 b = *(const float4*)(row + 4);
            float4 c = *(const float4*)(row + 8);
            float v[12] = { a.x, a.y, a.z, a.w, b.x, b.y, b.z, b.w,
                            c.x, c.y, c.z, c.w };
            float r[4];
#pragma unroll
            for (int i = 0; i < 4; ++i) {
                float acc = 0.0f;
#pragma unroll
                for (int d = 0; d < KW; ++d)
                    acc = fmaf(W[d], v[i + d], acc);
                r[i] = tanh_pos(acc);
            }
            *(float4*)(outn + s * SDIM + 4 * l) = make_float4(r[0], r[1], r[2], r[3]);
        }
    }
}

extern "C" void kernel_launch(void* const* d_in, const int* in_sizes, int n_in,
                              void* d_out, int out_size)
{
    const float* points = (const float*)d_in[0];
    float* out = (float*)d_out;

    size_t smem = SMEM_F * sizeof(float);   // ~21.8 KB
    cudaFuncSetAttribute(plotline2_kernel,
                         cudaFuncAttributeMaxDynamicSharedMemorySize, (int)smem);
    plotline2_kernel<<<NIMG * SLICES, BT, smem>>>(points, out);
}

// round 14
// speedup vs baseline: 1.0256x; 1.0256x over previous
#include <cuda_runtime.h>
#include <math.h>

// Problem constants (N=128 images, P=16 control points, S=128 grid)
#define NIMG 128
#define NP   16
#define NSEG (NP-1)            // 15 segments
#define SDIM 128
#define RAD  4                 // 9-tap Gaussian: dropped taps <= 1.1e-7 (safe vs 1e-3 tol)
#define KW   (2*RAD+1)

#define BT     256             // threads per CTA
#define SLICES 8               // CTAs per image
#define SR     16              // output rows per CTA
#define LR     (SR + 2*RAD)    // 24 histogram rows per slice (with halo)
#define HP     132             // hist y pitch (y in 0..128), mult of 4
#define M1P    140             // m1 pitch, mult of 4 (cols 0..136; stage2 writes 4..132)
#define PTS_F  (NP*2)          // 32 floats of control points
#define HS_F   (LR*HP)         // 3168
#define M1_F   (SR*M1P)        // 2240
#define SMEM_F (HS_F + M1_F + PTS_F)   // 5440 floats = 21.76 KB -> 8 CTAs/SM

// tanh(x) for x>=0; for x<=0.01, tanh(x)=x within 3.3e-7 abs
__device__ __forceinline__ float tanh_pos(float x) {
    if (x > 0.01f) {
        float e = __expf(x + x);                  // inf-safe: e=inf -> result 1
        x = 1.0f - __fdividef(2.0f, e + 1.0f);
    }
    return x;
}

__global__ __launch_bounds__(BT, 8)
void plotline2_kernel(const float* __restrict__ points, float* __restrict__ out)
{
    extern __shared__ float sm[];
    float* hs  = sm;                 // [LR][HP]
    float* m1  = sm + HS_F;          // [SR][M1P]; col c = conv-x at y = c-4
    float* pts = sm + HS_F + M1_F;   // [NP*2]

    const int n   = blockIdx.x >> 3;
    const int q   = blockIdx.x & 7;
    const int s0  = q * SR;
    const int tid = threadIdx.x;

    // Compile-time taps exp(-d^2) -> FFMA immediates
    constexpr float W[KW] = {
        1.1253517471925912e-7f, 1.2340980408667956e-4f, 0.018315638888734179f,
        0.36787944117144233f, 1.0f, 0.36787944117144233f,
        0.018315638888734179f, 1.2340980408667956e-4f, 1.1253517471925912e-7f
    };

    // ---- zero hs (full) + m1 left halo (cols 0..3 of each row) + preload points ----
    {
        float4 z = make_float4(0.f, 0.f, 0.f, 0.f);
        float4* h4 = (float4*)hs;
        for (int i = tid; i < HS_F / 4; i += BT) h4[i] = z;
        if (tid < SR) *(float4*)&m1[tid * M1P] = z;        // cols 0..3
        if (tid < PTS_F) pts[tid] = points[n * PTS_F + tid];
    }
    __syncthreads();

    // ---- stage 1: interpolate 1920 points, histogram those in our x-window ----
    // Segment-fixed mapping: thread (tid<240) owns seg = tid%15, steps
    // i = tid/15 + 16j.  Endpoint loads hoisted; fi += 16.0f is exact so
    // t = fi/128 is bit-identical to the reference's i/128.
    const float inv = 1.0f / (float)SDIM;
    const int lrbase = s0 - RAD;
    if (tid < 240) {
        int seg = tid % NSEG;
        int bi  = tid / NSEG;              // 0..15
        float x0 = pts[seg * 2 + 0];
        float y0 = pts[seg * 2 + 1];
        float x1 = pts[seg * 2 + 2];
        float y1 = pts[seg * 2 + 3];
        float fi = (float)bi;
#pragma unroll
        for (int j = 0; j < 8; ++j) {
            float t   = __fmul_rn(fi, inv);       // exact
            float omt = 1.0f - t;                 // exact
            // match XLA: mul, mul, add — no fma contraction
            float x = __fadd_rn(__fmul_rn(omt, x0), __fmul_rn(t, x1));
            int ix = (int)rintf(x);               // round-half-to-even, 0..128
            int lr = ix - lrbase;
            if ((unsigned)lr < (unsigned)LR) {    // early-out (~81% skip)
                float y = __fadd_rn(__fmul_rn(omt, y0), __fmul_rn(t, y1));
                int iy = (int)rintf(y);
                atomicAdd(&hs[lr * HP + iy], 1.0f);
            }
            fi += 16.0f;
        }
    }
    __syncthreads();

    // ---- stage 2: conv over x: m1[s][y+4] = sum_d W[d]*hs[s+d][y] ----
    // 4-row groups; lanes -> consecutive y (stride 1, conflict-free).
    for (int item = tid; item < 4 * 129; item += BT) {
        int g = item / 129;                // row group 0..3
        int y = item - g * 129;            // 0..128
        int sb = g * 4;
        float v[4 + KW - 1];               // 12
#pragma unroll
        for (int j = 0; j < 4 + KW - 1; ++j)
            v[j] = hs[(sb + j) * HP + y];
#pragma unroll
        for (int i = 0; i < 4; ++i) {
            float acc = 0.0f;
#pragma unroll
            for (int d = 0; d < KW; ++d)
                acc = fmaf(W[d], v[i + d], acc);
            m1[(sb + i) * M1P + (y + RAD)] = acc;
        }
    }
    __syncthreads();

    // ---- stage 3: conv over t + tanh -> DIRECT coalesced gmem store ----
    // Warp w handles rows s = w and w+8. Lane l -> t = 4l..4l+3:
    // three aligned LDS.128 (conflict-free), one STG.128 per row
    // (warp covers the full 512B row).
    {
        const int w = tid >> 5;
        const int l = tid & 31;
        float* outn = out + ((size_t)n * SDIM + s0) * SDIM;
#pragma unroll
        for (int rr = 0; rr < 2; ++rr) {
            int s = w + rr * 8;
            const float* row = m1 + s * M1P + 4 * l;
            float4 a = *(const float4*)(row);
            float4 b = *(const float4*)(row + 4);
            float4 c = *(const float4*)(row + 8);
            float v[12] = { a.x, a.y, a.z, a.w, b.x, b.y, b.z, b.w,
                            c.x, c.y, c.z, c.w };
            float r[4];
#pragma unroll
            for (int i = 0; i < 4; ++i) {
                float acc = 0.0f;
#pragma unroll
                for (int d = 0; d < KW; ++d)
                    acc = fmaf(W[d], v[i + d], acc);
                r[i] = tanh_pos(acc);
            }
            *(float4*)(outn + s * SDIM + 4 * l) = make_float4(r[0], r[1], r[2], r[3]);
        }
    }
}

extern "C" void kernel_launch(void* const* d_in, const int* in_sizes, int n_in,
                              void* d_out, int out_size)
{
    const float* points = (const float*)d_in[0];
    float* out = (float*)d_out;

    size_t smem = SMEM_F * sizeof(float);   // ~21.8 KB
    cudaFuncSetAttribute(plotline2_kernel,
                         cudaFuncAttributeMaxDynamicSharedMemorySize, (int)smem);
    plotline2_kernel<<<NIMG * SLICES, BT, smem>>>(points, out);
}

// round 15
// speedup vs baseline: 1.0753x; 1.0484x over previous
#include <cuda_runtime.h>
#include <math.h>

// Problem constants (N=128 images, P=16 control points, S=128 grid)
#define NIMG 128
#define NP   16
#define NSEG (NP-1)            // 15 segments
#define SDIM 128
#define RAD  4                 // 9-tap Gaussian: dropped taps <= 1.1e-7 (safe vs 1e-3 tol)
#define KW   (2*RAD+1)

#define BT     256             // threads per CTA
#define SLICES 8               // CTAs per image
#define SR     16              // output rows per CTA
#define LR     (SR + 2*RAD)    // 24 histogram rows per slice (with halo)
#define HP     132             // hist y pitch (y in 0..128; 129..131 zero), mult of 4
#define M1P    140             // m1 pitch, mult of 4 (cols 0..135 read; 136..139 pad)
#define PTS_F  (NP*2)
#define HS_F   (LR*HP)         // 3168
#define M1_F   (SR*M1P)        // 2240
#define SMEM_F (HS_F + M1_F + PTS_F)   // 5440 floats = 21.76 KB -> 8 CTAs/SM

typedef unsigned long long u64;

// ---- packed f32x2 helpers (PTX-only; ptxas never auto-fuses) ----
__device__ __forceinline__ u64 pack2(float lo, float hi) {
    u64 r; asm("mov.b64 %0,{%1,%2};" : "=l"(r) : "f"(lo), "f"(hi)); return r;
}
__device__ __forceinline__ void unpack2(u64 v, float& lo, float& hi) {
    asm("mov.b64 {%0,%1},%2;" : "=f"(lo), "=f"(hi) : "l"(v));
}
__device__ __forceinline__ u64 fma2(u64 a, u64 b, u64 c) {
    u64 d; asm("fma.rn.f32x2 %0,%1,%2,%3;" : "=l"(d) : "l"(a), "l"(b), "l"(c)); return d;
}

// tanh(x) for x>=0; for x<=0.01, tanh(x)=x within 3.3e-7 abs
__device__ __forceinline__ float tanh_pos(float x) {
    if (x > 0.01f) {
        float e = __expf(x + x);                  // inf-safe: e=inf -> result 1
        x = 1.0f - __fdividef(2.0f, e + 1.0f);
    }
    return x;
}

__global__ __launch_bounds__(BT, 8)
void plotline2_kernel(const float* __restrict__ points, float* __restrict__ out)
{
    extern __shared__ float sm[];
    float* hs  = sm;                 // [LR][HP]
    float* m1  = sm + HS_F;          // [SR][M1P]; col c = conv-x at y = c-4
    float* pts = sm + HS_F + M1_F;   // [NP*2]

    const int n   = blockIdx.x >> 3;
    const int q   = blockIdx.x & 7;
    const int s0  = q * SR;
    const int tid = threadIdx.x;

    // Compile-time taps exp(-d^2)
    constexpr float W[KW] = {
        1.1253517471925912e-7f, 1.2340980408667956e-4f, 0.018315638888734179f,
        0.36787944117144233f, 1.0f, 0.36787944117144233f,
        0.018315638888734179f, 1.2340980408667956e-4f, 1.1253517471925912e-7f
    };
    // Packed (replicated) taps; warp-uniform, built once
    u64 Wp[KW];
#pragma unroll
    for (int d = 0; d < KW; ++d) Wp[d] = pack2(W[d], W[d]);

    // ---- zero hs (full) + m1 halo cols 0..3 and 132..135 + preload points ----
    {
        float4 z = make_float4(0.f, 0.f, 0.f, 0.f);
        float4* h4 = (float4*)hs;
        for (int i = tid; i < HS_F / 4; i += BT) h4[i] = z;
        if (tid < SR) {
            *(float4*)&m1[tid * M1P]       = z;   // cols 0..3
            *(float4*)&m1[tid * M1P + 132] = z;   // cols 132..135 (132..133 rewritten)
        }
        if (tid < PTS_F) pts[tid] = points[n * PTS_F + tid];
    }
    __syncthreads();

    // ---- stage 1: interpolate 1920 points, histogram those in our x-window ----
    // Segment-fixed mapping: thread (tid<240) owns seg = tid%15, steps
    // i = tid/15 + 16j; fi += 16 is exact so t = fi/128 matches reference.
    const float inv = 1.0f / (float)SDIM;
    const int lrbase = s0 - RAD;
    if (tid < 240) {
        int seg = tid % NSEG;
        int bi  = tid / NSEG;              // 0..15
        float x0 = pts[seg * 2 + 0];
        float y0 = pts[seg * 2 + 1];
        float x1 = pts[seg * 2 + 2];
        float y1 = pts[seg * 2 + 3];
        float fi = (float)bi;
#pragma unroll
        for (int j = 0; j < 8; ++j) {
            float t   = __fmul_rn(fi, inv);       // exact
            float omt = 1.0f - t;                 // exact
            // match XLA: mul, mul, add — no fma contraction
            float x = __fadd_rn(__fmul_rn(omt, x0), __fmul_rn(t, x1));
            int ix = (int)rintf(x);               // round-half-to-even, 0..128
            int lr = ix - lrbase;
            if ((unsigned)lr < (unsigned)LR) {    // early-out (~81% skip)
                float y = __fadd_rn(__fmul_rn(omt, y0), __fmul_rn(t, y1));
                int iy = (int)rintf(y);
                atomicAdd(&hs[lr * HP + iy], 1.0f);
            }
            fi += 16.0f;
        }
    }
    __syncthreads();

    // ---- stage 2: conv over x, packed over y-pairs ----
    // item = (g, yp): rows sb=4g..4g+3, y = 2yp, 2yp+1 (yp<=64 -> y<=129;
    // hist col 129 is zero so m1 col 133 correctly evaluates to 0).
    // LDS.64 of hs[row][y..y+1] is directly the packed operand; result
    // stores as one STS.64 to m1 cols y+4..y+5.
    for (int item = tid; item < 4 * 65; item += BT) {      // 260 items
        int g  = item / 65;
        int yp = item - g * 65;
        int y  = 2 * yp;
        int sb = g * 4;
        u64 acc[4] = {0ull, 0ull, 0ull, 0ull};
#pragma unroll
        for (int j = 0; j < 4 + KW - 1; ++j) {             // 12 rows
            u64 v = *(const u64*)&hs[(sb + j) * HP + y];
#pragma unroll
            for (int i = 0; i < 4; ++i) {
                int d = j - i;
                if (d >= 0 && d < KW) acc[i] = fma2(Wp[d], v, acc[i]);
            }
        }
#pragma unroll
        for (int i = 0; i < 4; ++i)
            *(u64*)&m1[(sb + i) * M1P + (y + RAD)] = acc[i];
    }
    __syncthreads();

    // ---- stage 3: conv over t, packed over the (s, s+8) row pair; tanh;
    //      direct coalesced gmem store ----
    // Warp w: rows s=w and s=w+8. Lane l -> t = 4l..4l+3: three aligned
    // LDS.128 per row (conflict-free), one STG.128 per row (full 512B row).
    {
        const int w = tid >> 5;
        const int l = tid & 31;
        float* outn = out + ((size_t)n * SDIM + s0) * SDIM;
        const float* rowA = m1 + w * M1P + 4 * l;
        const float* rowB = rowA + 8 * M1P;
        float4 a0 = *(const float4*)(rowA);
        float4 a1 = *(const float4*)(rowA + 4);
        float4 a2 = *(const float4*)(rowA + 8);
        float4 b0 = *(const float4*)(rowB);
        float4 b1 = *(const float4*)(rowB + 4);
        float4 b2 = *(const float4*)(rowB + 8);
        u64 v[12] = {
            pack2(a0.x, b0.x), pack2(a0.y, b0.y), pack2(a0.z, b0.z), pack2(a0.w, b0.w),
            pack2(a1.x, b1.x), pack2(a1.y, b1.y), pack2(a1.z, b1.z), pack2(a1.w, b1.w),
            pack2(a2.x, b2.x), pack2(a2.y, b2.y), pack2(a2.z, b2.z), pack2(a2.w, b2.w)
        };
        u64 acc[4] = {0ull, 0ull, 0ull, 0ull};
#pragma unroll
        for (int j = 0; j < 4 + KW - 1; ++j) {
#pragma unroll
            for (int i = 0; i < 4; ++i) {
                int d = j - i;
                if (d >= 0 && d < KW) acc[i] = fma2(Wp[d], v[j], acc[i]);
            }
        }
        float rA[4], rB[4];
#pragma unroll
        for (int i = 0; i < 4; ++i) {
            unpack2(acc[i], rA[i], rB[i]);
            rA[i] = tanh_pos(rA[i]);
            rB[i] = tanh_pos(rB[i]);
        }
        *(float4*)(outn + w * SDIM + 4 * l)       = make_float4(rA[0], rA[1], rA[2], rA[3]);
        *(float4*)(outn + (w + 8) * SDIM + 4 * l) = make_float4(rB[0], rB[1], rB[2], rB[3]);
    }
}

extern "C" void kernel_launch(void* const* d_in, const int* in_sizes, int n_in,
                              void* d_out, int out_size)
{
    const float* points = (const float*)d_in[0];
    float* out = (float*)d_out;

    size_t smem = SMEM_F * sizeof(float);   // ~21.8 KB
    cudaFuncSetAttribute(plotline2_kernel,
                         cudaFuncAttributeMaxDynamicSharedMemorySize, (int)smem);
    plotline2_kernel<<<NIMG * SLICES, BT, smem>>>(points, out);
}